// round 10
// baseline (speedup 1.0000x reference)
#include <cuda_runtime.h>

// GRAPE: 20 commuting X-rotations collapse to one rotation, Theta = sum(a)*DT/2.
// 256 MiB pure stream, pinned at ~74% DRAM across 8 access-pattern configs.
//
// R9 -> R10: persistent single-wave grid. 888 CTAs x 256 thr = 6 CTAs/SM
// on 148 SMs -> exactly one wave, zero wave transitions (was ~9 waves of
// 8192 CTAs; each transition drains/refills the DRAM queue). Contiguous
// pair-split kept (first 444 CTAs = pair A, rest = pair B); each thread
// grid-strides over its pair's row with front-batched loads per iteration.
//
//   pair A: (r0, m1) -> out0r = c*r0 + s*m1 ; out1i = c*m1 - s*r0
//   pair B: (r1, m0) -> out1r = c*r1 + s*m0 ; out0i = c*m0 - s*r1

#define NUM_STEPS 20
#define DT_HALF   (0.5f * (1.0f / 20.0f))
#define BATCH     8388608

#define CTAS_PER_PAIR 444
#define THREADS       256

__global__ __launch_bounds__(THREADS) void grape_kernel(
    const float* __restrict__ amps,
    const float* __restrict__ sr,
    const float* __restrict__ si,
    float* __restrict__ out)
{
    float theta = 0.0f;
#pragma unroll
    for (int k = 0; k < NUM_STEPS; k++) theta += __ldg(&amps[k]);
    theta *= DT_HALF;
    const float c = cosf(theta);
    const float s = sinf(theta);

    const int n4 = BATCH / 4;                    // 2,097,152 float4 per row

    const float4* pa;
    const float4* pb;
    float4* po1;                                 // c*a + s*b
    float4* po2;                                 // c*b - s*a
    int cta;

    if (blockIdx.x < CTAS_PER_PAIR) {
        // pair A: (r0, m1) -> out0r, out1i
        cta = blockIdx.x;
        pa  = (const float4*)sr;                          // r0
        pb  = (const float4*)(si + (size_t)BATCH);        // m1
        po1 = (float4*)out;                               // out0r
        po2 = (float4*)(out + 3 * (size_t)BATCH);         // out1i
    } else {
        // pair B: (r1, m0) -> out1r, out0i
        cta = blockIdx.x - CTAS_PER_PAIR;
        pa  = (const float4*)(sr + (size_t)BATCH);        // r1
        pb  = (const float4*)si;                          // m0
        po1 = (float4*)(out + (size_t)BATCH);             // out1r
        po2 = (float4*)(out + 2 * (size_t)BATCH);         // out0i
    }

    const int stride = CTAS_PER_PAIR * THREADS;  // 113,664 float4 per sweep
    int i = cta * THREADS + threadIdx.x;

    // Grid-stride, 2 iterations deep with front-batched loads (MLP=4).
    for (; i + stride < n4; i += 2 * stride) {
        const int j = i + stride;
        float4 a0 = __ldg(&pa[i]);
        float4 b0 = __ldg(&pb[i]);
        float4 a1 = __ldg(&pa[j]);
        float4 b1 = __ldg(&pb[j]);

        float4 o1, o2;
        o1.x = fmaf(c, a0.x,  s * b0.x);  o2.x = fmaf(c, b0.x, -s * a0.x);
        o1.y = fmaf(c, a0.y,  s * b0.y);  o2.y = fmaf(c, b0.y, -s * a0.y);
        o1.z = fmaf(c, a0.z,  s * b0.z);  o2.z = fmaf(c, b0.z, -s * a0.z);
        o1.w = fmaf(c, a0.w,  s * b0.w);  o2.w = fmaf(c, b0.w, -s * a0.w);
        po1[i] = o1;
        po2[i] = o2;

        float4 p1, p2;
        p1.x = fmaf(c, a1.x,  s * b1.x);  p2.x = fmaf(c, b1.x, -s * a1.x);
        p1.y = fmaf(c, a1.y,  s * b1.y);  p2.y = fmaf(c, b1.y, -s * a1.y);
        p1.z = fmaf(c, a1.z,  s * b1.z);  p2.z = fmaf(c, b1.z, -s * a1.z);
        p1.w = fmaf(c, a1.w,  s * b1.w);  p2.w = fmaf(c, b1.w, -s * a1.w);
        po1[j] = p1;
        po2[j] = p2;
    }
    // Tail (at most one sweep).
    if (i < n4) {
        float4 a0 = __ldg(&pa[i]);
        float4 b0 = __ldg(&pb[i]);
        float4 o1, o2;
        o1.x = fmaf(c, a0.x,  s * b0.x);  o2.x = fmaf(c, b0.x, -s * a0.x);
        o1.y = fmaf(c, a0.y,  s * b0.y);  o2.y = fmaf(c, b0.y, -s * a0.y);
        o1.z = fmaf(c, a0.z,  s * b0.z);  o2.z = fmaf(c, b0.z, -s * a0.z);
        o1.w = fmaf(c, a0.w,  s * b0.w);  o2.w = fmaf(c, b0.w, -s * a0.w);
        po1[i] = o1;
        po2[i] = o2;
    }
}

extern "C" void kernel_launch(void* const* d_in, const int* in_sizes, int n_in,
                              void* d_out, int out_size)
{
    const float* amps = (const float*)d_in[0];  // [20]
    const float* sr   = (const float*)d_in[1];  // [2, B]
    const float* si   = (const float*)d_in[2];  // [2, B]
    float* out        = (float*)d_out;          // [2, 2, B]

    grape_kernel<<<2 * CTAS_PER_PAIR, THREADS>>>(amps, sr, si, out);
}

// round 11
// speedup vs baseline: 1.0449x; 1.0449x over previous
#include <cuda_runtime.h>

// GRAPE: 20 commuting X-rotations collapse to one rotation, Theta = sum(a)*DT/2.
// 256 MiB pure stream at the GB300 mixed-R/W HBM roofline (~6.2 TB/s eff).
//
// R10 -> R11: persistent grid regressed (regs 40, issue 10.8%) — reverted.
// Final family = contiguous pair-split, ILP=1, float4, __ldg, plain stores
// (the only config that hits 43.5us; measured twice). Last untried knob:
// block=1024 for the widest contiguous per-block DRAM footprint (16KB per
// stream). Otherwise byte-identical to the winner.
//
//   pair A: (r0, m1) -> out0r = c*r0 + s*m1 ; out1i = c*m1 - s*r0
//   pair B: (r1, m0) -> out1r = c*r1 + s*m0 ; out0i = c*m0 - s*r1

#define NUM_STEPS 20
#define DT_HALF   (0.5f * (1.0f / 20.0f))
#define BATCH     8388608

__global__ __launch_bounds__(1024) void grape_kernel(
    const float* __restrict__ amps,
    const float* __restrict__ sr,
    const float* __restrict__ si,
    float* __restrict__ out)
{
    float theta = 0.0f;
#pragma unroll
    for (int k = 0; k < NUM_STEPS; k++) theta += __ldg(&amps[k]);
    theta *= DT_HALF;
    const float c = cosf(theta);
    const float s = sinf(theta);

    const int n4  = BATCH / 4;                 // 2,097,152 float4 per row
    const int tid = blockIdx.x * blockDim.x + threadIdx.x;

    if (tid < n4) {
        // ---- pair A: (r0, m1) -> out0r, out1i ----
        const int i = tid;
        const float4* sr0 = (const float4*)sr;
        const float4* si1 = (const float4*)(si + (size_t)BATCH);
        float4* out0r = (float4*)out;
        float4* out1i = (float4*)(out + 3 * (size_t)BATCH);

        float4 a = __ldg(&sr0[i]);   // r0
        float4 b = __ldg(&si1[i]);   // m1

        float4 o1, o2;
        o1.x = fmaf(c, a.x,  s * b.x);  o2.x = fmaf(c, b.x, -s * a.x);
        o1.y = fmaf(c, a.y,  s * b.y);  o2.y = fmaf(c, b.y, -s * a.y);
        o1.z = fmaf(c, a.z,  s * b.z);  o2.z = fmaf(c, b.z, -s * a.z);
        o1.w = fmaf(c, a.w,  s * b.w);  o2.w = fmaf(c, b.w, -s * a.w);

        out0r[i] = o1;
        out1i[i] = o2;
    } else {
        // ---- pair B: (r1, m0) -> out1r, out0i ----
        const int i = tid - n4;
        const float4* sr1 = (const float4*)(sr + (size_t)BATCH);
        const float4* si0 = (const float4*)si;
        float4* out1r = (float4*)(out + (size_t)BATCH);
        float4* out0i = (float4*)(out + 2 * (size_t)BATCH);

        float4 a = __ldg(&sr1[i]);   // r1
        float4 b = __ldg(&si0[i]);   // m0

        float4 o1, o2;
        o1.x = fmaf(c, a.x,  s * b.x);  o2.x = fmaf(c, b.x, -s * a.x);
        o1.y = fmaf(c, a.y,  s * b.y);  o2.y = fmaf(c, b.y, -s * a.y);
        o1.z = fmaf(c, a.z,  s * b.z);  o2.z = fmaf(c, b.z, -s * a.z);
        o1.w = fmaf(c, a.w,  s * b.w);  o2.w = fmaf(c, b.w, -s * a.w);

        out1r[i] = o1;
        out0i[i] = o2;
    }
}

extern "C" void kernel_launch(void* const* d_in, const int* in_sizes, int n_in,
                              void* d_out, int out_size)
{
    const float* amps = (const float*)d_in[0];  // [20]
    const float* sr   = (const float*)d_in[1];  // [2, B]
    const float* si   = (const float*)d_in[2];  // [2, B]
    float* out        = (float*)d_out;          // [2, 2, B]

    const int n4 = BATCH / 4;
    const int threads = 1024;
    const int blocks = (2 * n4) / threads;      // 4096
    grape_kernel<<<blocks, threads>>>(amps, sr, si, out);
}

// round 12
// speedup vs baseline: 1.0576x; 1.0121x over previous
#include <cuda_runtime.h>

// GRAPE: 20 commuting X-rotations collapse to one rotation, Theta = sum(a)*DT/2.
// 256 MiB pure stream at the GB300 mixed-R/W HBM roofline (~6.2 TB/s eff).
//
// R11 -> R12: block-size sweep showed smaller blocks win (256:36.9us,
// 512:37.1us, 1024:40.5us kernel) — more concurrent address windows spread
// across L2 slices/DRAM channels. Final sweep point: block=128 (16384
// blocks). Everything else byte-identical to the 43.5us winner family
// (contiguous pair-split, ILP=1, float4, __ldg, plain stores).
//
//   pair A: (r0, m1) -> out0r = c*r0 + s*m1 ; out1i = c*m1 - s*r0
//   pair B: (r1, m0) -> out1r = c*r1 + s*m0 ; out0i = c*m0 - s*r1

#define NUM_STEPS 20
#define DT_HALF   (0.5f * (1.0f / 20.0f))
#define BATCH     8388608

__global__ __launch_bounds__(128) void grape_kernel(
    const float* __restrict__ amps,
    const float* __restrict__ sr,
    const float* __restrict__ si,
    float* __restrict__ out)
{
    float theta = 0.0f;
#pragma unroll
    for (int k = 0; k < NUM_STEPS; k++) theta += __ldg(&amps[k]);
    theta *= DT_HALF;
    const float c = cosf(theta);
    const float s = sinf(theta);

    const int n4  = BATCH / 4;                 // 2,097,152 float4 per row
    const int tid = blockIdx.x * blockDim.x + threadIdx.x;

    if (tid < n4) {
        // ---- pair A: (r0, m1) -> out0r, out1i ----
        const int i = tid;
        const float4* sr0 = (const float4*)sr;
        const float4* si1 = (const float4*)(si + (size_t)BATCH);
        float4* out0r = (float4*)out;
        float4* out1i = (float4*)(out + 3 * (size_t)BATCH);

        float4 a = __ldg(&sr0[i]);   // r0
        float4 b = __ldg(&si1[i]);   // m1

        float4 o1, o2;
        o1.x = fmaf(c, a.x,  s * b.x);  o2.x = fmaf(c, b.x, -s * a.x);
        o1.y = fmaf(c, a.y,  s * b.y);  o2.y = fmaf(c, b.y, -s * a.y);
        o1.z = fmaf(c, a.z,  s * b.z);  o2.z = fmaf(c, b.z, -s * a.z);
        o1.w = fmaf(c, a.w,  s * b.w);  o2.w = fmaf(c, b.w, -s * a.w);

        out0r[i] = o1;
        out1i[i] = o2;
    } else {
        // ---- pair B: (r1, m0) -> out1r, out0i ----
        const int i = tid - n4;
        const float4* sr1 = (const float4*)(sr + (size_t)BATCH);
        const float4* si0 = (const float4*)si;
        float4* out1r = (float4*)(out + (size_t)BATCH);
        float4* out0i = (float4*)(out + 2 * (size_t)BATCH);

        float4 a = __ldg(&sr1[i]);   // r1
        float4 b = __ldg(&si0[i]);   // m0

        float4 o1, o2;
        o1.x = fmaf(c, a.x,  s * b.x);  o2.x = fmaf(c, b.x, -s * a.x);
        o1.y = fmaf(c, a.y,  s * b.y);  o2.y = fmaf(c, b.y, -s * a.y);
        o1.z = fmaf(c, a.z,  s * b.z);  o2.z = fmaf(c, b.z, -s * a.z);
        o1.w = fmaf(c, a.w,  s * b.w);  o2.w = fmaf(c, b.w, -s * a.w);

        out1r[i] = o1;
        out0i[i] = o2;
    }
}

extern "C" void kernel_launch(void* const* d_in, const int* in_sizes, int n_in,
                              void* d_out, int out_size)
{
    const float* amps = (const float*)d_in[0];  // [20]
    const float* sr   = (const float*)d_in[1];  // [2, B]
    const float* si   = (const float*)d_in[2];  // [2, B]
    float* out        = (float*)d_out;          // [2, 2, B]

    const int n4 = BATCH / 4;
    const int threads = 128;
    const int blocks = (2 * n4) / threads;      // 32768
    grape_kernel<<<blocks, threads>>>(amps, sr, si, out);
}

// round 13
// speedup vs baseline: 1.0621x; 1.0043x over previous
#include <cuda_runtime.h>

// GRAPE: 20 commuting X-rotations collapse to ONE rotation (they share the
// Pauli-X generator): Theta = sum(a_k) * DT/2, U = cos(Theta) I - i sin(Theta) X.
// The whole scan becomes 4 fused FMAs per column -> pure 256 MiB stream.
//
// FINAL (R13 = R3 verbatim, the measured optimum, 43.5us twice):
//   - contiguous pair-split: grid halves own independent 2-read/2-write
//     stream pairs (fewer interleaved DRAM streams per scheduling window)
//   - ILP=1, float4, __ldg, plain stores, 256-thread blocks
// Sweeps proven neutral-or-worse: ILP=2 (both forms), 256-bit LDG/STG,
// .nc / streaming / L2-evict-priority hints (inert across graph replays),
// even/odd stream interleave, persistent single-wave grid, block in
// {128, 512, 1024}. Kernel sits at the GB300 mixed-R/W HBM roofline
// (~6.2 TB/s effective); traffic is irreducible.
//
//   pair A: (r0, m1) -> out0r = c*r0 + s*m1 ; out1i = c*m1 - s*r0
//   pair B: (r1, m0) -> out1r = c*r1 + s*m0 ; out0i = c*m0 - s*r1

#define NUM_STEPS 20
#define DT_HALF   (0.5f * (1.0f / 20.0f))
#define BATCH     8388608

__global__ __launch_bounds__(256) void grape_kernel(
    const float* __restrict__ amps,
    const float* __restrict__ sr,
    const float* __restrict__ si,
    float* __restrict__ out)
{
    float theta = 0.0f;
#pragma unroll
    for (int k = 0; k < NUM_STEPS; k++) theta += __ldg(&amps[k]);
    theta *= DT_HALF;
    const float c = cosf(theta);
    const float s = sinf(theta);

    const int n4  = BATCH / 4;                 // 2,097,152 float4 per row
    const int tid = blockIdx.x * blockDim.x + threadIdx.x;

    if (tid < n4) {
        // ---- pair A: (r0, m1) -> out0r, out1i ----
        const int i = tid;
        const float4* sr0 = (const float4*)sr;
        const float4* si1 = (const float4*)(si + (size_t)BATCH);
        float4* out0r = (float4*)out;
        float4* out1i = (float4*)(out + 3 * (size_t)BATCH);

        float4 a = __ldg(&sr0[i]);   // r0
        float4 b = __ldg(&si1[i]);   // m1

        float4 o1, o2;
        o1.x = fmaf(c, a.x,  s * b.x);  o2.x = fmaf(c, b.x, -s * a.x);
        o1.y = fmaf(c, a.y,  s * b.y);  o2.y = fmaf(c, b.y, -s * a.y);
        o1.z = fmaf(c, a.z,  s * b.z);  o2.z = fmaf(c, b.z, -s * a.z);
        o1.w = fmaf(c, a.w,  s * b.w);  o2.w = fmaf(c, b.w, -s * a.w);

        out0r[i] = o1;
        out1i[i] = o2;
    } else {
        // ---- pair B: (r1, m0) -> out1r, out0i ----
        const int i = tid - n4;
        const float4* sr1 = (const float4*)(sr + (size_t)BATCH);
        const float4* si0 = (const float4*)si;
        float4* out1r = (float4*)(out + (size_t)BATCH);
        float4* out0i = (float4*)(out + 2 * (size_t)BATCH);

        float4 a = __ldg(&sr1[i]);   // r1
        float4 b = __ldg(&si0[i]);   // m0

        float4 o1, o2;
        o1.x = fmaf(c, a.x,  s * b.x);  o2.x = fmaf(c, b.x, -s * a.x);
        o1.y = fmaf(c, a.y,  s * b.y);  o2.y = fmaf(c, b.y, -s * a.y);
        o1.z = fmaf(c, a.z,  s * b.z);  o2.z = fmaf(c, b.z, -s * a.z);
        o1.w = fmaf(c, a.w,  s * b.w);  o2.w = fmaf(c, b.w, -s * a.w);

        out1r[i] = o1;
        out0i[i] = o2;
    }
}

extern "C" void kernel_launch(void* const* d_in, const int* in_sizes, int n_in,
                              void* d_out, int out_size)
{
    const float* amps = (const float*)d_in[0];  // [20]
    const float* sr   = (const float*)d_in[1];  // [2, B]
    const float* si   = (const float*)d_in[2];  // [2, B]
    float* out        = (float*)d_out;          // [2, 2, B]

    const int n4 = BATCH / 4;
    const int threads = 256;
    const int blocks = (2 * n4) / threads;      // 16384
    grape_kernel<<<blocks, threads>>>(amps, sr, si, out);
}

// round 14
// speedup vs baseline: 1.0941x; 1.0301x over previous
#include <cuda_runtime.h>

// GRAPE: 20 commuting X-rotations collapse to ONE rotation:
// Theta = sum(a_k)*DT/2, U = cos(Theta) I - i sin(Theta) X -> 4 FMAs/column,
// pure 256 MiB stream at the GB300 mixed-R/W HBM roofline (~6.2 TB/s eff).
//
// R13 -> R14: clean isolation of streaming stores (__stcs) on the winner
// config (contiguous pair-split, ILP=1, float4, __ldg, 256 thr). All prior
// stcs tests were confounded with other regressions. Hypothesis: avoiding
// L2 write-allocate reduces write-drain vs next-replay read contention in
// the back-to-back graph-replay timing loop.
//
//   pair A: (r0, m1) -> out0r = c*r0 + s*m1 ; out1i = c*m1 - s*r0
//   pair B: (r1, m0) -> out1r = c*r1 + s*m0 ; out0i = c*m0 - s*r1

#define NUM_STEPS 20
#define DT_HALF   (0.5f * (1.0f / 20.0f))
#define BATCH     8388608

__global__ __launch_bounds__(256) void grape_kernel(
    const float* __restrict__ amps,
    const float* __restrict__ sr,
    const float* __restrict__ si,
    float* __restrict__ out)
{
    float theta = 0.0f;
#pragma unroll
    for (int k = 0; k < NUM_STEPS; k++) theta += __ldg(&amps[k]);
    theta *= DT_HALF;
    const float c = cosf(theta);
    const float s = sinf(theta);

    const int n4  = BATCH / 4;                 // 2,097,152 float4 per row
    const int tid = blockIdx.x * blockDim.x + threadIdx.x;

    if (tid < n4) {
        // ---- pair A: (r0, m1) -> out0r, out1i ----
        const int i = tid;
        const float4* sr0 = (const float4*)sr;
        const float4* si1 = (const float4*)(si + (size_t)BATCH);
        float4* out0r = (float4*)out;
        float4* out1i = (float4*)(out + 3 * (size_t)BATCH);

        float4 a = __ldg(&sr0[i]);   // r0
        float4 b = __ldg(&si1[i]);   // m1

        float4 o1, o2;
        o1.x = fmaf(c, a.x,  s * b.x);  o2.x = fmaf(c, b.x, -s * a.x);
        o1.y = fmaf(c, a.y,  s * b.y);  o2.y = fmaf(c, b.y, -s * a.y);
        o1.z = fmaf(c, a.z,  s * b.z);  o2.z = fmaf(c, b.z, -s * a.z);
        o1.w = fmaf(c, a.w,  s * b.w);  o2.w = fmaf(c, b.w, -s * a.w);

        __stcs(&out0r[i], o1);
        __stcs(&out1i[i], o2);
    } else {
        // ---- pair B: (r1, m0) -> out1r, out0i ----
        const int i = tid - n4;
        const float4* sr1 = (const float4*)(sr + (size_t)BATCH);
        const float4* si0 = (const float4*)si;
        float4* out1r = (float4*)(out + (size_t)BATCH);
        float4* out0i = (float4*)(out + 2 * (size_t)BATCH);

        float4 a = __ldg(&sr1[i]);   // r1
        float4 b = __ldg(&si0[i]);   // m0

        float4 o1, o2;
        o1.x = fmaf(c, a.x,  s * b.x);  o2.x = fmaf(c, b.x, -s * a.x);
        o1.y = fmaf(c, a.y,  s * b.y);  o2.y = fmaf(c, b.y, -s * a.y);
        o1.z = fmaf(c, a.z,  s * b.z);  o2.z = fmaf(c, b.z, -s * a.z);
        o1.w = fmaf(c, a.w,  s * b.w);  o2.w = fmaf(c, b.w, -s * a.w);

        __stcs(&out1r[i], o1);
        __stcs(&out0i[i], o2);
    }
}

extern "C" void kernel_launch(void* const* d_in, const int* in_sizes, int n_in,
                              void* d_out, int out_size)
{
    const float* amps = (const float*)d_in[0];  // [20]
    const float* sr   = (const float*)d_in[1];  // [2, B]
    const float* si   = (const float*)d_in[2];  // [2, B]
    float* out        = (float*)d_out;          // [2, 2, B]

    const int n4 = BATCH / 4;
    const int threads = 256;
    const int blocks = (2 * n4) / threads;      // 16384
    grape_kernel<<<blocks, threads>>>(amps, sr, si, out);
}